// round 1
// baseline (speedup 1.0000x reference)
#include <cuda_runtime.h>
#include <math.h>

// Problem constants
#define SQ 1024
#define HD 768
#define NH 12
#define DH 64
#define NB 8
#define BHCOUNT (NB*NH)   // 96
#define MROWS (NB*SQ)     // 8192

// Scratch (device globals: allocation-free)
__device__ float g_q[BHCOUNT*SQ*DH];
__device__ float g_k[BHCOUNT*SQ*DH];
__device__ float g_v[BHCOUNT*SQ*DH];
__device__ float g_ao[MROWS*HD];

// ---------------------------------------------------------------------------
// SGEMM: C = A[8192x768] * W[768x768] + bias[768]
// 128x128 tile, K-tile 8, 256 threads, 8x8 per thread (spread mapping).
// mode 0: C = Cout, plain [M,N] row-major
// mode 1/2/3: C = g_q/g_k/g_v, head-major layout [(b*NH+h)*SQ + s]*DH + dd
//             (for mode 0 the A operand is g_ao, param A ignored)
// ---------------------------------------------------------------------------
__global__ __launch_bounds__(256) void gemm_bias(
    const float* __restrict__ A, const float* __restrict__ W,
    const float* __restrict__ bias, float* __restrict__ Cout, int mode)
{
    __shared__ float As[8][128];
    __shared__ float Bs[8][128];

    const float* Ap = (mode == 0) ? g_ao : A;
    float* C = (mode == 0) ? Cout : (mode == 1 ? g_q : (mode == 2 ? g_k : g_v));

    const int tid = threadIdx.x;
    const int tx = tid & 15, ty = tid >> 4;
    const int bx = blockIdx.x, by = blockIdx.y;

    const int arow = tid >> 1;            // 0..127
    const int acol = (tid & 1) * 4;       // 0 or 4
    const int brow = tid >> 5;            // 0..7
    const int bcol = (tid & 31) * 4;      // 0..124

    const float* aptr = Ap + (size_t)(by * 128 + arow) * HD + acol;
    const float* bptr = W + (size_t)brow * HD + bx * 128 + bcol;

    float acc[8][8];
#pragma unroll
    for (int i = 0; i < 8; ++i)
#pragma unroll
        for (int j = 0; j < 8; ++j) acc[i][j] = 0.0f;

    for (int kb = 0; kb < HD / 8; ++kb) {
        float4 av = *(const float4*)(aptr + kb * 8);
        float4 bv = *(const float4*)(bptr + (size_t)kb * 8 * HD);
        __syncthreads();
        As[acol + 0][arow] = av.x;
        As[acol + 1][arow] = av.y;
        As[acol + 2][arow] = av.z;
        As[acol + 3][arow] = av.w;
        *(float4*)&Bs[brow][bcol] = bv;
        __syncthreads();
#pragma unroll
        for (int k = 0; k < 8; ++k) {
            float4 a0 = *(const float4*)&As[k][ty * 4];
            float4 a1 = *(const float4*)&As[k][64 + ty * 4];
            float4 b0 = *(const float4*)&Bs[k][tx * 4];
            float4 b1 = *(const float4*)&Bs[k][64 + tx * 4];
            float ar[8] = {a0.x, a0.y, a0.z, a0.w, a1.x, a1.y, a1.z, a1.w};
            float br[8] = {b0.x, b0.y, b0.z, b0.w, b1.x, b1.y, b1.z, b1.w};
#pragma unroll
            for (int i = 0; i < 8; ++i)
#pragma unroll
                for (int j = 0; j < 8; ++j)
                    acc[i][j] = fmaf(ar[i], br[j], acc[i][j]);
        }
    }

    // epilogue: rows {ty*4+i, 64+ty*4+i}, cols {tx*4+j, 64+tx*4+j}
#pragma unroll
    for (int ih = 0; ih < 2; ++ih) {
#pragma unroll
        for (int i = 0; i < 4; ++i) {
            int m = by * 128 + ih * 64 + ty * 4 + i;
#pragma unroll
            for (int jh = 0; jh < 2; ++jh) {
                int ncol = bx * 128 + jh * 64 + tx * 4;
                float4 bb = *(const float4*)&bias[ncol];
                float4 r;
                r.x = acc[ih * 4 + i][jh * 4 + 0] + bb.x;
                r.y = acc[ih * 4 + i][jh * 4 + 1] + bb.y;
                r.z = acc[ih * 4 + i][jh * 4 + 2] + bb.z;
                r.w = acc[ih * 4 + i][jh * 4 + 3] + bb.w;
                if (mode == 0) {
                    *(float4*)&C[(size_t)m * HD + ncol] = r;
                } else {
                    int b = m >> 10, s = m & 1023;
                    int hh = ncol >> 6, dd = ncol & 63;
                    *(float4*)&C[(((size_t)(b * NH + hh) * SQ + s) * DH) + dd] = r;
                }
            }
        }
    }
}

// ---------------------------------------------------------------------------
// Fused flash attention per (b, h, 64-query tile).
// Threads 256, layout 16x16; thread (ty,tx) owns score rows ty*4+i, cols tx*4+j.
// smem: Qs[r][dd] (68 stride), Ks[dd][c], Vs[c][dd], Ps[c][r]
// ---------------------------------------------------------------------------
#define ATTN_SMEM (4 * 64 * 68 * 4)

__global__ __launch_bounds__(256) void attn_kernel(
    const float* __restrict__ bias, const int* __restrict__ mask)
{
    extern __shared__ float sm[];
    float* Qs = sm;                 // [64][68]  (row, dd)
    float* Ks = sm + 64 * 68;       // [64][68]  (dd, col)
    float* Vs = sm + 2 * 64 * 68;   // [64][68]  (col, dd)
    float* Ps = sm + 3 * 64 * 68;   // [64][68]  (col, row)

    const int bh = blockIdx.x;
    const int b = bh / NH, hh = bh - b * NH;
    const int q0 = blockIdx.y * 64;
    const int tid = threadIdx.x;
    const int tx = tid & 15, ty = tid >> 4;

    const float* qg = g_q + ((size_t)bh * SQ + q0) * DH;
    const float* kg = g_k + (size_t)bh * SQ * DH;
    const float* vg = g_v + (size_t)bh * SQ * DH;

    // load Q tile
    for (int i = tid; i < 64 * 16; i += 256) {
        int r = i >> 4, d4 = (i & 15) * 4;
        *(float4*)&Qs[r * 68 + d4] = *(const float4*)&qg[r * 64 + d4];
    }

    float m_i[4], l_i[4], o[4][4];
#pragma unroll
    for (int i = 0; i < 4; ++i) {
        m_i[i] = -1e30f;
        l_i[i] = 0.0f;
#pragma unroll
        for (int j = 0; j < 4; ++j) o[i][j] = 0.0f;
    }
    const float scale = 0.125f;  // 64^-0.5

    for (int kb = 0; kb < SQ / 64; ++kb) {
        const int k0 = kb * 64;
        __syncthreads();  // previous PV finished reading Vs/Ps
        // load K (transposed) and V
        for (int i = tid; i < 64 * 16; i += 256) {
            int c = i >> 4, d4 = (i & 15) * 4;
            float4 kv = *(const float4*)&kg[(size_t)(k0 + c) * 64 + d4];
            Ks[(d4 + 0) * 68 + c] = kv.x;
            Ks[(d4 + 1) * 68 + c] = kv.y;
            Ks[(d4 + 2) * 68 + c] = kv.z;
            Ks[(d4 + 3) * 68 + c] = kv.w;
            *(float4*)&Vs[c * 68 + d4] = *(const float4*)&vg[(size_t)(k0 + c) * 64 + d4];
        }
        // prefetch bias + mask (overlaps with score compute)
        float bv[4][4];
        int mk[4][4];
#pragma unroll
        for (int i = 0; i < 4; ++i) {
            int qrow = q0 + ty * 4 + i;
            size_t base = ((size_t)(b * SQ + qrow)) * SQ + k0 + tx * 4;
#pragma unroll
            for (int j = 0; j < 4; ++j) {
                bv[i][j] = bias[(base + j) * NH + hh];
                mk[i][j] = mask[base + j];
            }
        }
        __syncthreads();

        // scores S = Q K^T
        float s[4][4];
#pragma unroll
        for (int i = 0; i < 4; ++i)
#pragma unroll
            for (int j = 0; j < 4; ++j) s[i][j] = 0.0f;

#pragma unroll 4
        for (int d4 = 0; d4 < 64; d4 += 4) {
            float qa[4][4];
#pragma unroll
            for (int i = 0; i < 4; ++i) {
                float4 t = *(const float4*)&Qs[(ty * 4 + i) * 68 + d4];
                qa[i][0] = t.x; qa[i][1] = t.y; qa[i][2] = t.z; qa[i][3] = t.w;
            }
#pragma unroll
            for (int u = 0; u < 4; ++u) {
                float4 k4 = *(const float4*)&Ks[(d4 + u) * 68 + tx * 4];
#pragma unroll
                for (int i = 0; i < 4; ++i) {
                    s[i][0] = fmaf(qa[i][u], k4.x, s[i][0]);
                    s[i][1] = fmaf(qa[i][u], k4.y, s[i][1]);
                    s[i][2] = fmaf(qa[i][u], k4.z, s[i][2]);
                    s[i][3] = fmaf(qa[i][u], k4.w, s[i][3]);
                }
            }
        }

        // scale + bias + mask, online softmax
#pragma unroll
        for (int i = 0; i < 4; ++i) {
#pragma unroll
            for (int j = 0; j < 4; ++j)
                s[i][j] = mk[i][j] ? 1e-14f : fmaf(s[i][j], scale, bv[i][j]);

            float mx = fmaxf(fmaxf(s[i][0], s[i][1]), fmaxf(s[i][2], s[i][3]));
#pragma unroll
            for (int off = 8; off >= 1; off >>= 1)
                mx = fmaxf(mx, __shfl_xor_sync(0xffffffffu, mx, off, 16));
            float mnew = fmaxf(m_i[i], mx);
            float alpha = __expf(m_i[i] - mnew);
            m_i[i] = mnew;
            float rs = 0.0f;
#pragma unroll
            for (int j = 0; j < 4; ++j) {
                s[i][j] = __expf(s[i][j] - mnew);
                rs += s[i][j];
            }
#pragma unroll
            for (int off = 8; off >= 1; off >>= 1)
                rs += __shfl_xor_sync(0xffffffffu, rs, off, 16);
            l_i[i] = l_i[i] * alpha + rs;
#pragma unroll
            for (int j = 0; j < 4; ++j) o[i][j] *= alpha;
            // store P transposed: Ps[c][r]
#pragma unroll
            for (int j = 0; j < 4; ++j)
                Ps[(tx * 4 + j) * 68 + ty * 4 + i] = s[i][j];
        }
        __syncthreads();

        // O += P V
#pragma unroll 8
        for (int c = 0; c < 64; ++c) {
            float4 v4 = *(const float4*)&Vs[c * 68 + tx * 4];
#pragma unroll
            for (int i = 0; i < 4; ++i) {
                float p = Ps[c * 68 + ty * 4 + i];
                o[i][0] = fmaf(p, v4.x, o[i][0]);
                o[i][1] = fmaf(p, v4.y, o[i][1]);
                o[i][2] = fmaf(p, v4.z, o[i][2]);
                o[i][3] = fmaf(p, v4.w, o[i][3]);
            }
        }
    }

    // write back normalized O into [B,S,H] scratch for output projection
#pragma unroll
    for (int i = 0; i < 4; ++i) {
        float inv = 1.0f / l_i[i];
        float4 r;
        r.x = o[i][0] * inv; r.y = o[i][1] * inv;
        r.z = o[i][2] * inv; r.w = o[i][3] * inv;
        int qrow = q0 + ty * 4 + i;
        *(float4*)&g_ao[(size_t)(b * SQ + qrow) * HD + hh * 64 + tx * 4] = r;
    }
}

// ---------------------------------------------------------------------------
extern "C" void kernel_launch(void* const* d_in, const int* in_sizes, int n_in,
                              void* d_out, int out_size)
{
    const float* h  = (const float*)d_in[0];
    const float* ab = (const float*)d_in[1];
    const int*   mk = (const int*)d_in[2];
    const float* Wq = (const float*)d_in[3];
    const float* bq = (const float*)d_in[4];
    const float* Wk = (const float*)d_in[5];
    const float* bk = (const float*)d_in[6];
    const float* Wv = (const float*)d_in[7];
    const float* bv = (const float*)d_in[8];
    const float* Wo = (const float*)d_in[9];
    const float* bo = (const float*)d_in[10];
    float* out = (float*)d_out;

    cudaFuncSetAttribute(attn_kernel,
                         cudaFuncAttributeMaxDynamicSharedMemorySize, ATTN_SMEM);

    dim3 gg(HD / 128, MROWS / 128);   // (6, 64)
    gemm_bias<<<gg, 256>>>(h, Wq, bq, nullptr, 1);
    gemm_bias<<<gg, 256>>>(h, Wk, bk, nullptr, 2);
    gemm_bias<<<gg, 256>>>(h, Wv, bv, nullptr, 3);
    attn_kernel<<<dim3(BHCOUNT, SQ / 64), 256, ATTN_SMEM>>>(ab, mk);
    gemm_bias<<<gg, 256>>>(nullptr, Wo, bo, out, 0);
}

// round 3
// speedup vs baseline: 1.7894x; 1.7894x over previous
#include <cuda_runtime.h>
#include <cstdint>

// Problem constants
#define SQ 1024
#define HD 768
#define NH 12
#define DH 64
#define NB 8
#define BHCOUNT (NB*NH)   // 96
#define MROWS (NB*SQ)     // 8192

// Scratch (device globals: allocation-free)
__device__ float g_q[BHCOUNT*SQ*DH];
__device__ float g_k[BHCOUNT*SQ*DH];
__device__ float g_v[BHCOUNT*SQ*DH];
__device__ float g_ao[MROWS*HD];

// ---------------------------------------------------------------------------
// tf32 mma.sync helpers (legacy tensor path; PTX-portable to compute_103)
// ---------------------------------------------------------------------------
__device__ __forceinline__ uint32_t f2tf(float x) {
    uint32_t r;
    asm("cvt.rna.tf32.f32 %0, %1;" : "=r"(r) : "f"(x));
    return r;
}

__device__ __forceinline__ void mma8(float* c,
                                     uint32_t a0, uint32_t a1, uint32_t a2, uint32_t a3,
                                     uint32_t b0, uint32_t b1) {
    asm volatile(
        "mma.sync.aligned.m16n8k8.row.col.f32.tf32.tf32.f32 "
        "{%0,%1,%2,%3}, {%4,%5,%6,%7}, {%8,%9}, {%0,%1,%2,%3};"
        : "+f"(c[0]), "+f"(c[1]), "+f"(c[2]), "+f"(c[3])
        : "r"(a0), "r"(a1), "r"(a2), "r"(a3), "r"(b0), "r"(b1));
}

// ---------------------------------------------------------------------------
// Projection GEMM: C[8192,768] = A[8192,768] * W[768,768] + bias
// 128x128 tile, 8 warps (2x4), warp tile 64x32, K-chunk 32, double buffered.
// A smem: [128][36] (pad), B smem (W rows): [32][132] (pad).
// mode 0: A=g_ao, C=Cout row-major.  mode 1/2/3: C=g_q/g_k/g_v head-major.
// ---------------------------------------------------------------------------
#define GA_STRIDE 36
#define GB_STRIDE 132
#define A_ST (128*GA_STRIDE)       // 4608 floats
#define B_ST (32*GB_STRIDE)        // 4224 floats
#define STAGE (A_ST + B_ST)        // 8832 floats
#define NCHUNK (HD/32)             // 24
#define GEMM_SMEM (2*STAGE*4)      // 70656 bytes

__global__ __launch_bounds__(256) void gemm_tc(
    const float* __restrict__ Ain, const float* __restrict__ W,
    const float* __restrict__ bias, float* __restrict__ Cout, int mode)
{
    extern __shared__ float sm[];
    const int tid = threadIdx.x;
    const int wid = tid >> 5, lane = tid & 31;
    const int wm = wid >> 2, wn = wid & 3;   // 2 x 4 warp grid
    const int g = lane >> 2, t = lane & 3;

    const float* A = (mode == 0) ? g_ao : Ain;
    float* C = (mode == 0) ? Cout : (mode == 1 ? g_q : (mode == 2 ? g_k : g_v));

    const int m0 = blockIdx.y * 128;
    const int n0 = blockIdx.x * 128;

    float acc[4][4][4];
#pragma unroll
    for (int i = 0; i < 4; ++i)
#pragma unroll
        for (int j = 0; j < 4; ++j)
#pragma unroll
            for (int r = 0; r < 4; ++r) acc[i][j][r] = 0.0f;

    // ---- chunk 0 load ----
    {
        float* As = sm;
        float* Bs = sm + A_ST;
#pragma unroll
        for (int it = 0; it < 4; ++it) {
            int idx = tid + it * 256;
            int ar = idx >> 3, ac = idx & 7;
            *(float4*)&As[ar * GA_STRIDE + ac * 4] =
                *(const float4*)&A[(size_t)(m0 + ar) * HD + ac * 4];
            int br = idx >> 5, bc = idx & 31;
            *(float4*)&Bs[br * GB_STRIDE + bc * 4] =
                *(const float4*)&W[(size_t)br * HD + n0 + bc * 4];
        }
    }
    __syncthreads();

    for (int c = 0; c < NCHUNK; ++c) {
        const int s = c & 1;
        float4 pa[4], pb[4];
        if (c + 1 < NCHUNK) {
            const int k0 = (c + 1) * 32;
#pragma unroll
            for (int it = 0; it < 4; ++it) {
                int idx = tid + it * 256;
                int ar = idx >> 3, ac = idx & 7;
                pa[it] = *(const float4*)&A[(size_t)(m0 + ar) * HD + k0 + ac * 4];
                int br = idx >> 5, bc = idx & 31;
                pb[it] = *(const float4*)&W[(size_t)(k0 + br) * HD + n0 + bc * 4];
            }
        }

        const float* As = sm + s * STAGE;
        const float* Bs = As + A_ST;
#pragma unroll
        for (int ks = 0; ks < 4; ++ks) {
            uint32_t af[4][4];
#pragma unroll
            for (int mf = 0; mf < 4; ++mf) {
                const float* p = As + (wm * 64 + mf * 16 + g) * GA_STRIDE + ks * 8 + t;
                af[mf][0] = f2tf(p[0]);
                af[mf][1] = f2tf(p[8 * GA_STRIDE]);
                af[mf][2] = f2tf(p[4]);
                af[mf][3] = f2tf(p[8 * GA_STRIDE + 4]);
            }
            uint32_t bf[4][2];
#pragma unroll
            for (int nf = 0; nf < 4; ++nf) {
                const float* p = Bs + (ks * 8 + t) * GB_STRIDE + wn * 32 + nf * 8 + g;
                bf[nf][0] = f2tf(p[0]);
                bf[nf][1] = f2tf(p[4 * GB_STRIDE]);
            }
#pragma unroll
            for (int mf = 0; mf < 4; ++mf)
#pragma unroll
                for (int nf = 0; nf < 4; ++nf)
                    mma8(acc[mf][nf], af[mf][0], af[mf][1], af[mf][2], af[mf][3],
                         bf[nf][0], bf[nf][1]);
        }
        __syncthreads();
        if (c + 1 < NCHUNK) {
            float* As2 = sm + (s ^ 1) * STAGE;
            float* Bs2 = As2 + A_ST;
#pragma unroll
            for (int it = 0; it < 4; ++it) {
                int idx = tid + it * 256;
                int ar = idx >> 3, ac = idx & 7;
                *(float4*)&As2[ar * GA_STRIDE + ac * 4] = pa[it];
                int br = idx >> 5, bc = idx & 31;
                *(float4*)&Bs2[br * GB_STRIDE + bc * 4] = pb[it];
            }
            __syncthreads();
        }
    }

    // ---- epilogue ----
#pragma unroll
    for (int mf = 0; mf < 4; ++mf) {
#pragma unroll
        for (int nf = 0; nf < 4; ++nf) {
            int r0 = m0 + wm * 64 + mf * 16 + g;
            int ncol = n0 + wn * 32 + nf * 8 + 2 * t;
            float b0 = bias[ncol], b1 = bias[ncol + 1];
            float2 v0 = make_float2(acc[mf][nf][0] + b0, acc[mf][nf][1] + b1);
            float2 v1 = make_float2(acc[mf][nf][2] + b0, acc[mf][nf][3] + b1);
            if (mode == 0) {
                *(float2*)&C[(size_t)r0 * HD + ncol] = v0;
                *(float2*)&C[(size_t)(r0 + 8) * HD + ncol] = v1;
            } else {
                int hh = ncol >> 6, dd = ncol & 63;
                int b = r0 >> 10, sidx = r0 & 1023;
                *(float2*)&C[(((size_t)(b * NH + hh) * SQ + sidx) * DH) + dd] = v0;
                *(float2*)&C[(((size_t)(b * NH + hh) * SQ + sidx + 8) * DH) + dd] = v1;
            }
        }
    }
}

// ---------------------------------------------------------------------------
// Flash attention with tf32 mma. 128 threads (4 warps), 64 q-rows per block.
// Warp w owns q-rows [16w, 16w+16). Per chunk of 64 k-positions:
//   S = Q K^T (mma), fold scale/bias/mask, online softmax in fragment layout,
//   P -> smem, O += P V (mma).
// smem: Qs[64][68], Ks[64][68], Vs[64][72], Ps[64][68]
// ---------------------------------------------------------------------------
#define QS_STR 68
#define VS_STR 72
#define ATTN_SMEM ((64*QS_STR*3 + 64*VS_STR) * 4)   // 70656 bytes

__global__ __launch_bounds__(128) void attn_kernel(
    const float* __restrict__ bias, const int* __restrict__ mask)
{
    extern __shared__ float sm[];
    float* Qs = sm;
    float* Ks = Qs + 64 * QS_STR;
    float* Vs = Ks + 64 * QS_STR;
    float* Ps = Vs + 64 * VS_STR;

    const int bh = blockIdx.x;
    const int b = bh / NH, hh = bh - b * NH;
    const int q0 = blockIdx.y * 64;
    const int tid = threadIdx.x;
    const int wid = tid >> 5, lane = tid & 31;
    const int g = lane >> 2, t = lane & 3;

    const float* qg = g_q + ((size_t)bh * SQ + q0) * DH;
    const float* kg = g_k + (size_t)bh * SQ * DH;
    const float* vg = g_v + (size_t)bh * SQ * DH;

    // Q tile load
#pragma unroll
    for (int it = 0; it < 8; ++it) {
        int idx = tid + it * 128;
        int r = idx >> 4, d4 = (idx & 15) * 4;
        *(float4*)&Qs[r * QS_STR + d4] = *(const float4*)&qg[r * 64 + d4];
    }

    // this thread's two rows
    const int r0 = q0 + wid * 16 + g;
    const int r1 = r0 + 8;
    const float* bias_r0 = bias + ((size_t)(b * SQ + r0) * SQ) * NH + hh;
    const float* bias_r1 = bias + ((size_t)(b * SQ + r1) * SQ) * NH + hh;
    const int* mask_r0 = mask + (size_t)(b * SQ + r0) * SQ;
    const int* mask_r1 = mask + (size_t)(b * SQ + r1) * SQ;

    float m0 = -1e30f, m1 = -1e30f, l0 = 0.0f, l1 = 0.0f;
    float oacc[8][4];
#pragma unroll
    for (int nf = 0; nf < 8; ++nf)
#pragma unroll
        for (int r = 0; r < 4; ++r) oacc[nf][r] = 0.0f;

    for (int kb = 0; kb < SQ / 64; ++kb) {
        const int k0 = kb * 64;
        __syncthreads();   // previous iteration's readers of Ks/Vs done
#pragma unroll
        for (int it = 0; it < 8; ++it) {
            int idx = tid + it * 128;
            int cc = idx >> 4, d4 = (idx & 15) * 4;
            *(float4*)&Ks[cc * QS_STR + d4] = *(const float4*)&kg[(size_t)(k0 + cc) * 64 + d4];
            *(float4*)&Vs[cc * VS_STR + d4] = *(const float4*)&vg[(size_t)(k0 + cc) * 64 + d4];
        }
        __syncthreads();

        // ---- S = Q K^T ----
        float sacc[8][4];
#pragma unroll
        for (int nf = 0; nf < 8; ++nf)
#pragma unroll
            for (int r = 0; r < 4; ++r) sacc[nf][r] = 0.0f;

#pragma unroll
        for (int ks = 0; ks < 8; ++ks) {
            const float* qp = Qs + (wid * 16 + g) * QS_STR + ks * 8 + t;
            uint32_t a0 = f2tf(qp[0]);
            uint32_t a1 = f2tf(qp[8 * QS_STR]);
            uint32_t a2 = f2tf(qp[4]);
            uint32_t a3 = f2tf(qp[8 * QS_STR + 4]);
#pragma unroll
            for (int nf = 0; nf < 8; ++nf) {
                const float* kp = Ks + (nf * 8 + g) * QS_STR + ks * 8 + t;
                mma8(sacc[nf], a0, a1, a2, a3, f2tf(kp[0]), f2tf(kp[4]));
            }
        }

        // ---- fold scale + bias + mask ----
#pragma unroll
        for (int nf = 0; nf < 8; ++nf) {
            int kc = k0 + nf * 8 + 2 * t;
            int2 mk0 = *(const int2*)&mask_r0[kc];
            int2 mk1 = *(const int2*)&mask_r1[kc];
            float bi00 = bias_r0[(size_t)kc * NH];
            float bi01 = bias_r0[(size_t)(kc + 1) * NH];
            float bi10 = bias_r1[(size_t)kc * NH];
            float bi11 = bias_r1[(size_t)(kc + 1) * NH];
            sacc[nf][0] = mk0.x ? 1e-14f : fmaf(sacc[nf][0], 0.125f, bi00);
            sacc[nf][1] = mk0.y ? 1e-14f : fmaf(sacc[nf][1], 0.125f, bi01);
            sacc[nf][2] = mk1.x ? 1e-14f : fmaf(sacc[nf][2], 0.125f, bi10);
            sacc[nf][3] = mk1.y ? 1e-14f : fmaf(sacc[nf][3], 0.125f, bi11);
        }

        // ---- online softmax (rows r0, r1) ----
        float mx0 = -1e30f, mx1 = -1e30f;
#pragma unroll
        for (int nf = 0; nf < 8; ++nf) {
            mx0 = fmaxf(mx0, fmaxf(sacc[nf][0], sacc[nf][1]));
            mx1 = fmaxf(mx1, fmaxf(sacc[nf][2], sacc[nf][3]));
        }
        mx0 = fmaxf(mx0, __shfl_xor_sync(0xffffffffu, mx0, 1));
        mx0 = fmaxf(mx0, __shfl_xor_sync(0xffffffffu, mx0, 2));
        mx1 = fmaxf(mx1, __shfl_xor_sync(0xffffffffu, mx1, 1));
        mx1 = fmaxf(mx1, __shfl_xor_sync(0xffffffffu, mx1, 2));
        float mn0 = fmaxf(m0, mx0), mn1 = fmaxf(m1, mx1);
        float al0 = __expf(m0 - mn0), al1 = __expf(m1 - mn1);
        m0 = mn0; m1 = mn1;
        float rs0 = 0.0f, rs1 = 0.0f;
#pragma unroll
        for (int nf = 0; nf < 8; ++nf) {
            sacc[nf][0] = __expf(sacc[nf][0] - mn0);
            sacc[nf][1] = __expf(sacc[nf][1] - mn0);
            sacc[nf][2] = __expf(sacc[nf][2] - mn1);
            sacc[nf][3] = __expf(sacc[nf][3] - mn1);
            rs0 += sacc[nf][0] + sacc[nf][1];
            rs1 += sacc[nf][2] + sacc[nf][3];
        }
        rs0 += __shfl_xor_sync(0xffffffffu, rs0, 1);
        rs0 += __shfl_xor_sync(0xffffffffu, rs0, 2);
        rs1 += __shfl_xor_sync(0xffffffffu, rs1, 1);
        rs1 += __shfl_xor_sync(0xffffffffu, rs1, 2);
        l0 = l0 * al0 + rs0;
        l1 = l1 * al1 + rs1;
#pragma unroll
        for (int nf = 0; nf < 8; ++nf) {
            oacc[nf][0] *= al0; oacc[nf][1] *= al0;
            oacc[nf][2] *= al1; oacc[nf][3] *= al1;
        }

        // ---- P -> smem (warp-local rows) ----
        {
            int rl0 = wid * 16 + g;
#pragma unroll
            for (int nf = 0; nf < 8; ++nf) {
                int kc = nf * 8 + 2 * t;
                *(float2*)&Ps[rl0 * QS_STR + kc] = make_float2(sacc[nf][0], sacc[nf][1]);
                *(float2*)&Ps[(rl0 + 8) * QS_STR + kc] = make_float2(sacc[nf][2], sacc[nf][3]);
            }
        }
        __syncwarp();

        // ---- O += P V ----
#pragma unroll
        for (int ks = 0; ks < 8; ++ks) {
            const float* pp = Ps + (wid * 16 + g) * QS_STR + ks * 8 + t;
            uint32_t a0 = f2tf(pp[0]);
            uint32_t a1 = f2tf(pp[8 * QS_STR]);
            uint32_t a2 = f2tf(pp[4]);
            uint32_t a3 = f2tf(pp[8 * QS_STR + 4]);
#pragma unroll
            for (int nf = 0; nf < 8; ++nf) {
                const float* vp = Vs + (ks * 8 + t) * VS_STR + nf * 8 + g;
                mma8(oacc[nf], a0, a1, a2, a3, f2tf(vp[0]), f2tf(vp[4 * VS_STR]));
            }
        }
    }

    // ---- normalize + write to g_ao ----
    float inv0 = 1.0f / l0, inv1 = 1.0f / l1;
#pragma unroll
    for (int nf = 0; nf < 8; ++nf) {
        int col = hh * 64 + nf * 8 + 2 * t;
        *(float2*)&g_ao[(size_t)(b * SQ + r0) * HD + col] =
            make_float2(oacc[nf][0] * inv0, oacc[nf][1] * inv0);
        *(float2*)&g_ao[(size_t)(b * SQ + r1) * HD + col] =
            make_float2(oacc[nf][2] * inv1, oacc[nf][3] * inv1);
    }
}

// ---------------------------------------------------------------------------
extern "C" void kernel_launch(void* const* d_in, const int* in_sizes, int n_in,
                              void* d_out, int out_size)
{
    const float* h  = (const float*)d_in[0];
    const float* ab = (const float*)d_in[1];
    const int*   mk = (const int*)d_in[2];
    const float* Wq = (const float*)d_in[3];
    const float* bq = (const float*)d_in[4];
    const float* Wk = (const float*)d_in[5];
    const float* bk = (const float*)d_in[6];
    const float* Wv = (const float*)d_in[7];
    const float* bv = (const float*)d_in[8];
    const float* Wo = (const float*)d_in[9];
    const float* bo = (const float*)d_in[10];
    float* out = (float*)d_out;

    cudaFuncSetAttribute(gemm_tc,
                         cudaFuncAttributeMaxDynamicSharedMemorySize, GEMM_SMEM);
    cudaFuncSetAttribute(attn_kernel,
                         cudaFuncAttributeMaxDynamicSharedMemorySize, ATTN_SMEM);

    dim3 gg(HD / 128, MROWS / 128);   // (6, 64)
    gemm_tc<<<gg, 256, GEMM_SMEM>>>(h, Wq, bq, g_q, 1);
    gemm_tc<<<gg, 256, GEMM_SMEM>>>(h, Wk, bk, g_k, 2);
    gemm_tc<<<gg, 256, GEMM_SMEM>>>(h, Wv, bv, g_v, 3);
    attn_kernel<<<dim3(BHCOUNT, SQ / 64), 128, ATTN_SMEM>>>(ab, mk);
    gemm_tc<<<gg, 256, GEMM_SMEM>>>(nullptr, Wo, bo, out, 0);
}

// round 4
// speedup vs baseline: 2.3258x; 1.2997x over previous
#include <cuda_runtime.h>
#include <cstdint>

// Problem constants
#define SQ 1024
#define HD 768
#define NH 12
#define DH 64
#define NB 8
#define BHCOUNT (NB*NH)   // 96
#define MROWS (NB*SQ)     // 8192

// Scratch (device globals: allocation-free)
// g_q/g_k/g_v hold tf32-converted bit patterns (stored as float)
__device__ float g_q[BHCOUNT*SQ*DH];
__device__ float g_k[BHCOUNT*SQ*DH];
__device__ float g_v[BHCOUNT*SQ*DH];
__device__ float g_ao[MROWS*HD];

// ---------------------------------------------------------------------------
// helpers
// ---------------------------------------------------------------------------
__device__ __forceinline__ uint32_t f2tf(float x) {
    uint32_t r;
    asm("cvt.rna.tf32.f32 %0, %1;" : "=r"(r) : "f"(x));
    return r;
}
__device__ __forceinline__ float f2tff(float x) {
    return __uint_as_float(f2tf(x));
}

__device__ __forceinline__ void mma8(float* c,
                                     uint32_t a0, uint32_t a1, uint32_t a2, uint32_t a3,
                                     uint32_t b0, uint32_t b1) {
    asm volatile(
        "mma.sync.aligned.m16n8k8.row.col.f32.tf32.tf32.f32 "
        "{%0,%1,%2,%3}, {%4,%5,%6,%7}, {%8,%9}, {%0,%1,%2,%3};"
        : "+f"(c[0]), "+f"(c[1]), "+f"(c[2]), "+f"(c[3])
        : "r"(a0), "r"(a1), "r"(a2), "r"(a3), "r"(b0), "r"(b1));
}

__device__ __forceinline__ uint32_t smem_u32(const void* p) {
    uint32_t a;
    asm("{ .reg .u64 t; cvta.to.shared.u64 t, %1; cvt.u32.u64 %0, t; }"
        : "=r"(a) : "l"(p));
    return a;
}
__device__ __forceinline__ void cpa16(uint32_t dst, const void* src) {
    asm volatile("cp.async.cg.shared.global [%0], [%1], 16;" :: "r"(dst), "l"(src));
}
#define CP_COMMIT() asm volatile("cp.async.commit_group;" ::: "memory")
#define CP_WAIT0()  asm volatile("cp.async.wait_group 0;" ::: "memory")

// ---------------------------------------------------------------------------
// Projection GEMM: C[8192,768] = A * W + bias.
// mode 1: fused QKV (blockIdx.z selects W/bias; out g_q/g_k/g_v, tf32 bits,
//         head-major). mode 0: A=g_ao, C=Cout row-major fp32.
// 128x128 tile, 8 warps (2x4), warp tile 64x32, K-chunk 32, double buffered.
// smem tiles hold tf32 bit patterns (converted at store).
// ---------------------------------------------------------------------------
#define GA_STRIDE 36
#define GB_STRIDE 132
#define A_ST (128*GA_STRIDE)
#define B_ST (32*GB_STRIDE)
#define STAGE (A_ST + B_ST)
#define NCHUNK (HD/32)
#define GEMM_SMEM (2*STAGE*4)

__global__ __launch_bounds__(256) void gemm_tc(
    const float* __restrict__ Ain,
    const float* __restrict__ W0, const float* __restrict__ W1, const float* __restrict__ W2,
    const float* __restrict__ b0p, const float* __restrict__ b1p, const float* __restrict__ b2p,
    float* __restrict__ Cout, int mode)
{
    extern __shared__ float sm[];
    const int tid = threadIdx.x;
    const int wid = tid >> 5, lane = tid & 31;
    const int wm = wid >> 2, wn = wid & 3;
    const int g = lane >> 2, t = lane & 3;
    const int z = (mode == 1) ? blockIdx.z : 0;

    const float* A = (mode == 0) ? g_ao : Ain;
    const float* W = (z == 0) ? W0 : (z == 1 ? W1 : W2);
    const float* bias = (z == 0) ? b0p : (z == 1 ? b1p : b2p);
    float* C = (mode == 0) ? Cout : (z == 0 ? g_q : (z == 1 ? g_k : g_v));

    const int m0 = blockIdx.y * 128;
    const int n0 = blockIdx.x * 128;

    float acc[4][4][4];
#pragma unroll
    for (int i = 0; i < 4; ++i)
#pragma unroll
        for (int j = 0; j < 4; ++j)
#pragma unroll
            for (int r = 0; r < 4; ++r) acc[i][j][r] = 0.0f;

    // chunk 0 load (convert to tf32 bits at store)
    {
        float* As = sm;
        float* Bs = sm + A_ST;
#pragma unroll
        for (int it = 0; it < 4; ++it) {
            int idx = tid + it * 256;
            int ar = idx >> 3, ac = idx & 7;
            float4 av = *(const float4*)&A[(size_t)(m0 + ar) * HD + ac * 4];
            av.x = f2tff(av.x); av.y = f2tff(av.y); av.z = f2tff(av.z); av.w = f2tff(av.w);
            *(float4*)&As[ar * GA_STRIDE + ac * 4] = av;
            int br = idx >> 5, bc = idx & 31;
            float4 bv = *(const float4*)&W[(size_t)br * HD + n0 + bc * 4];
            bv.x = f2tff(bv.x); bv.y = f2tff(bv.y); bv.z = f2tff(bv.z); bv.w = f2tff(bv.w);
            *(float4*)&Bs[br * GB_STRIDE + bc * 4] = bv;
        }
    }
    __syncthreads();

    for (int c = 0; c < NCHUNK; ++c) {
        const int s = c & 1;
        float4 pa[4], pb[4];
        if (c + 1 < NCHUNK) {
            const int k0 = (c + 1) * 32;
#pragma unroll
            for (int it = 0; it < 4; ++it) {
                int idx = tid + it * 256;
                int ar = idx >> 3, ac = idx & 7;
                pa[it] = *(const float4*)&A[(size_t)(m0 + ar) * HD + k0 + ac * 4];
                int br = idx >> 5, bc = idx & 31;
                pb[it] = *(const float4*)&W[(size_t)(k0 + br) * HD + n0 + bc * 4];
            }
        }

        const float* As = sm + s * STAGE;
        const float* Bs = As + A_ST;
#pragma unroll
        for (int ks = 0; ks < 4; ++ks) {
            uint32_t af[4][4];
#pragma unroll
            for (int mf = 0; mf < 4; ++mf) {
                const float* p = As + (wm * 64 + mf * 16 + g) * GA_STRIDE + ks * 8 + t;
                af[mf][0] = __float_as_uint(p[0]);
                af[mf][1] = __float_as_uint(p[8 * GA_STRIDE]);
                af[mf][2] = __float_as_uint(p[4]);
                af[mf][3] = __float_as_uint(p[8 * GA_STRIDE + 4]);
            }
            uint32_t bf[4][2];
#pragma unroll
            for (int nf = 0; nf < 4; ++nf) {
                const float* p = Bs + (ks * 8 + t) * GB_STRIDE + wn * 32 + nf * 8 + g;
                bf[nf][0] = __float_as_uint(p[0]);
                bf[nf][1] = __float_as_uint(p[4 * GB_STRIDE]);
            }
#pragma unroll
            for (int mf = 0; mf < 4; ++mf)
#pragma unroll
                for (int nf = 0; nf < 4; ++nf)
                    mma8(acc[mf][nf], af[mf][0], af[mf][1], af[mf][2], af[mf][3],
                         bf[nf][0], bf[nf][1]);
        }
        __syncthreads();
        if (c + 1 < NCHUNK) {
            float* As2 = sm + (s ^ 1) * STAGE;
            float* Bs2 = As2 + A_ST;
#pragma unroll
            for (int it = 0; it < 4; ++it) {
                int idx = tid + it * 256;
                int ar = idx >> 3, ac = idx & 7;
                float4 av = pa[it];
                av.x = f2tff(av.x); av.y = f2tff(av.y); av.z = f2tff(av.z); av.w = f2tff(av.w);
                *(float4*)&As2[ar * GA_STRIDE + ac * 4] = av;
                int br = idx >> 5, bc = idx & 31;
                float4 bv = pb[it];
                bv.x = f2tff(bv.x); bv.y = f2tff(bv.y); bv.z = f2tff(bv.z); bv.w = f2tff(bv.w);
                *(float4*)&Bs2[br * GB_STRIDE + bc * 4] = bv;
            }
            __syncthreads();
        }
    }

    // epilogue
#pragma unroll
    for (int mf = 0; mf < 4; ++mf) {
#pragma unroll
        for (int nf = 0; nf < 4; ++nf) {
            int r0 = m0 + wm * 64 + mf * 16 + g;
            int ncol = n0 + wn * 32 + nf * 8 + 2 * t;
            float bb0 = bias[ncol], bb1 = bias[ncol + 1];
            float2 v0 = make_float2(acc[mf][nf][0] + bb0, acc[mf][nf][1] + bb1);
            float2 v1 = make_float2(acc[mf][nf][2] + bb0, acc[mf][nf][3] + bb1);
            if (mode == 0) {
                *(float2*)&C[(size_t)r0 * HD + ncol] = v0;
                *(float2*)&C[(size_t)(r0 + 8) * HD + ncol] = v1;
            } else {
                v0.x = f2tff(v0.x); v0.y = f2tff(v0.y);
                v1.x = f2tff(v1.x); v1.y = f2tff(v1.y);
                int hh = ncol >> 6, dd = ncol & 63;
                int b = r0 >> 10, sidx = r0 & 1023;
                *(float2*)&C[(((size_t)(b * NH + hh) * SQ + sidx) * DH) + dd] = v0;
                *(float2*)&C[(((size_t)(b * NH + hh) * SQ + sidx + 8) * DH) + dd] = v1;
            }
        }
    }
}

// ---------------------------------------------------------------------------
// Flash attention, tf32 mma. 256 threads (8 warps), 128 q-rows per block.
// K/V double-buffered via cp.async; bias/mask prefetched before S-mma;
// Q fragments resident in registers (tf32 bits already, from QKV gemm).
// smem (floats): K2[2][64*68], V2[2][64*72], Ps[128][68] (Q stage reuses Ps)
// ---------------------------------------------------------------------------
#define KSTR 68
#define VSTR 72
#define K_OFF(s)  ((s)*64*KSTR)
#define V_OFF(s)  (2*64*KSTR + (s)*64*VSTR)
#define P_OFF     (2*64*KSTR + 2*64*VSTR)
#define ATTN_FLOATS (P_OFF + 128*KSTR)
#define ATTN_SMEM (ATTN_FLOATS*4)   // 106496 bytes

__global__ __launch_bounds__(256) void attn_kernel(
    const float* __restrict__ bias, const int* __restrict__ mask)
{
    extern __shared__ float sm[];
    const uint32_t sb = smem_u32(sm);
    float* Ps = sm + P_OFF;

    const int bh = blockIdx.x;
    const int b = bh / NH, hh = bh - b * NH;
    const int q0 = blockIdx.y * 128;
    const int tid = threadIdx.x;
    const int wid = tid >> 5, lane = tid & 31;
    const int g = lane >> 2, t = lane & 3;
    const int rl = wid * 16 + g;            // local q-row (fragment row)

    const float* qg = g_q + ((size_t)bh * SQ + q0) * DH;
    const float* kg = g_k + (size_t)bh * SQ * DH;
    const float* vg = g_v + (size_t)bh * SQ * DH;

    // issue chunk-0 K/V cp.async first (overlaps Q staging)
#pragma unroll
    for (int it = 0; it < 4; ++it) {
        int idx = tid + it * 256;
        int row = idx >> 4, c4 = idx & 15;
        cpa16(sb + (uint32_t)(K_OFF(0) + row * KSTR + c4 * 4) * 4,
              kg + (size_t)row * 64 + c4 * 4);
        cpa16(sb + (uint32_t)(V_OFF(0) + row * VSTR + c4 * 4) * 4,
              vg + (size_t)row * 64 + c4 * 4);
    }
    CP_COMMIT();

    // stage Q tile (128x64) into Ps, then extract fragments to registers
#pragma unroll
    for (int it = 0; it < 8; ++it) {
        int idx = tid + it * 256;
        int row = idx >> 4, c4 = idx & 15;
        *(float4*)&Ps[row * KSTR + c4 * 4] = *(const float4*)&qg[(size_t)row * 64 + c4 * 4];
    }
    __syncthreads();
    uint32_t qf[8][4];
#pragma unroll
    for (int ks = 0; ks < 8; ++ks) {
        qf[ks][0] = __float_as_uint(Ps[rl * KSTR + ks * 8 + t]);
        qf[ks][1] = __float_as_uint(Ps[(rl + 8) * KSTR + ks * 8 + t]);
        qf[ks][2] = __float_as_uint(Ps[rl * KSTR + ks * 8 + t + 4]);
        qf[ks][3] = __float_as_uint(Ps[(rl + 8) * KSTR + ks * 8 + t + 4]);
    }
    CP_WAIT0();
    __syncthreads();   // chunk0 ready everywhere; all Q extractions done

    const int r0 = q0 + rl;
    const int r1 = r0 + 8;
    const float* bias_r0 = bias + ((size_t)(b * SQ + r0) * SQ) * NH + hh;
    const float* bias_r1 = bias + ((size_t)(b * SQ + r1) * SQ) * NH + hh;
    const int* mask_r0 = mask + (size_t)(b * SQ + r0) * SQ;
    const int* mask_r1 = mask + (size_t)(b * SQ + r1) * SQ;

    float m0 = -1e30f, m1 = -1e30f, l0 = 0.0f, l1 = 0.0f;
    float oacc[8][4];
#pragma unroll
    for (int nf = 0; nf < 8; ++nf)
#pragma unroll
        for (int r = 0; r < 4; ++r) oacc[nf][r] = 0.0f;

    for (int kb = 0; kb < SQ / 64; ++kb) {
        const int s = kb & 1;
        const int k0 = kb * 64;

        // ---- prefetch bias + mask (consumed after S-mma) ----
        float bp[8][4];
        int mp[8][4];
#pragma unroll
        for (int nf = 0; nf < 8; ++nf) {
            int kc = k0 + nf * 8 + 2 * t;
            int2 ma = *(const int2*)&mask_r0[kc];
            int2 mb = *(const int2*)&mask_r1[kc];
            mp[nf][0] = ma.x; mp[nf][1] = ma.y; mp[nf][2] = mb.x; mp[nf][3] = mb.y;
            bp[nf][0] = bias_r0[(size_t)kc * NH];
            bp[nf][1] = bias_r0[(size_t)(kc + 1) * NH];
            bp[nf][2] = bias_r1[(size_t)kc * NH];
            bp[nf][3] = bias_r1[(size_t)(kc + 1) * NH];
        }

        // ---- cp.async next K/V chunk ----
        if (kb + 1 < SQ / 64) {
            const int kn = k0 + 64;
#pragma unroll
            for (int it = 0; it < 4; ++it) {
                int idx = tid + it * 256;
                int row = idx >> 4, c4 = idx & 15;
                cpa16(sb + (uint32_t)(K_OFF(s ^ 1) + row * KSTR + c4 * 4) * 4,
                      kg + (size_t)(kn + row) * 64 + c4 * 4);
                cpa16(sb + (uint32_t)(V_OFF(s ^ 1) + row * VSTR + c4 * 4) * 4,
                      vg + (size_t)(kn + row) * 64 + c4 * 4);
            }
            CP_COMMIT();
        }

        // ---- S = Q K^T ----
        const float* Ksf = sm + K_OFF(s);
        float sacc[8][4];
#pragma unroll
        for (int nf = 0; nf < 8; ++nf)
#pragma unroll
            for (int r = 0; r < 4; ++r) sacc[nf][r] = 0.0f;
#pragma unroll
        for (int ks = 0; ks < 8; ++ks) {
#pragma unroll
            for (int nf = 0; nf < 8; ++nf) {
                const float* kp = Ksf + (nf * 8 + g) * KSTR + ks * 8 + t;
                mma8(sacc[nf], qf[ks][0], qf[ks][1], qf[ks][2], qf[ks][3],
                     __float_as_uint(kp[0]), __float_as_uint(kp[4]));
            }
        }

        // ---- fold scale + bias + mask ----
#pragma unroll
        for (int nf = 0; nf < 8; ++nf) {
            sacc[nf][0] = mp[nf][0] ? 1e-14f : fmaf(sacc[nf][0], 0.125f, bp[nf][0]);
            sacc[nf][1] = mp[nf][1] ? 1e-14f : fmaf(sacc[nf][1], 0.125f, bp[nf][1]);
            sacc[nf][2] = mp[nf][2] ? 1e-14f : fmaf(sacc[nf][2], 0.125f, bp[nf][2]);
            sacc[nf][3] = mp[nf][3] ? 1e-14f : fmaf(sacc[nf][3], 0.125f, bp[nf][3]);
        }

        // ---- online softmax (rows r0, r1) ----
        float mx0 = -1e30f, mx1 = -1e30f;
#pragma unroll
        for (int nf = 0; nf < 8; ++nf) {
            mx0 = fmaxf(mx0, fmaxf(sacc[nf][0], sacc[nf][1]));
            mx1 = fmaxf(mx1, fmaxf(sacc[nf][2], sacc[nf][3]));
        }
        mx0 = fmaxf(mx0, __shfl_xor_sync(0xffffffffu, mx0, 1));
        mx0 = fmaxf(mx0, __shfl_xor_sync(0xffffffffu, mx0, 2));
        mx1 = fmaxf(mx1, __shfl_xor_sync(0xffffffffu, mx1, 1));
        mx1 = fmaxf(mx1, __shfl_xor_sync(0xffffffffu, mx1, 2));
        float mn0 = fmaxf(m0, mx0), mn1 = fmaxf(m1, mx1);
        float al0 = __expf(m0 - mn0), al1 = __expf(m1 - mn1);
        m0 = mn0; m1 = mn1;
        float rs0 = 0.0f, rs1 = 0.0f;
#pragma unroll
        for (int nf = 0; nf < 8; ++nf) {
            sacc[nf][0] = __expf(sacc[nf][0] - mn0);
            sacc[nf][1] = __expf(sacc[nf][1] - mn0);
            sacc[nf][2] = __expf(sacc[nf][2] - mn1);
            sacc[nf][3] = __expf(sacc[nf][3] - mn1);
            rs0 += sacc[nf][0] + sacc[nf][1];
            rs1 += sacc[nf][2] + sacc[nf][3];
        }
        rs0 += __shfl_xor_sync(0xffffffffu, rs0, 1);
        rs0 += __shfl_xor_sync(0xffffffffu, rs0, 2);
        rs1 += __shfl_xor_sync(0xffffffffu, rs1, 1);
        rs1 += __shfl_xor_sync(0xffffffffu, rs1, 2);
        l0 = l0 * al0 + rs0;
        l1 = l1 * al1 + rs1;
#pragma unroll
        for (int nf = 0; nf < 8; ++nf) {
            oacc[nf][0] *= al0; oacc[nf][1] *= al0;
            oacc[nf][2] *= al1; oacc[nf][3] *= al1;
        }

        // ---- P (tf32 bits) -> smem, warp-local rows ----
#pragma unroll
        for (int nf = 0; nf < 8; ++nf) {
            int kc = nf * 8 + 2 * t;
            *(float2*)&Ps[rl * KSTR + kc] =
                make_float2(f2tff(sacc[nf][0]), f2tff(sacc[nf][1]));
            *(float2*)&Ps[(rl + 8) * KSTR + kc] =
                make_float2(f2tff(sacc[nf][2]), f2tff(sacc[nf][3]));
        }
        __syncwarp();

        // ---- O += P V ----
        const float* Vsf = sm + V_OFF(s);
#pragma unroll
        for (int ks = 0; ks < 8; ++ks) {
            const float* pp = Ps + rl * KSTR + ks * 8 + t;
            uint32_t a0 = __float_as_uint(pp[0]);
            uint32_t a1 = __float_as_uint(pp[8 * KSTR]);
            uint32_t a2 = __float_as_uint(pp[4]);
            uint32_t a3 = __float_as_uint(pp[8 * KSTR + 4]);
#pragma unroll
            for (int nf = 0; nf < 8; ++nf) {
                const float* vp = Vsf + (ks * 8 + t) * VSTR + nf * 8 + g;
                mma8(oacc[nf], a0, a1, a2, a3,
                     __float_as_uint(vp[0]), __float_as_uint(vp[4 * VSTR]));
            }
        }

        if (kb + 1 < SQ / 64) CP_WAIT0();
        __syncthreads();
    }

    // ---- normalize + write to g_ao (fp32) ----
    float inv0 = 1.0f / l0, inv1 = 1.0f / l1;
#pragma unroll
    for (int nf = 0; nf < 8; ++nf) {
        int col = hh * 64 + nf * 8 + 2 * t;
        *(float2*)&g_ao[(size_t)(b * SQ + r0) * HD + col] =
            make_float2(oacc[nf][0] * inv0, oacc[nf][1] * inv0);
        *(float2*)&g_ao[(size_t)(b * SQ + r1) * HD + col] =
            make_float2(oacc[nf][2] * inv1, oacc[nf][3] * inv1);
    }
}

// ---------------------------------------------------------------------------
extern "C" void kernel_launch(void* const* d_in, const int* in_sizes, int n_in,
                              void* d_out, int out_size)
{
    const float* h  = (const float*)d_in[0];
    const float* ab = (const float*)d_in[1];
    const int*   mk = (const int*)d_in[2];
    const float* Wq = (const float*)d_in[3];
    const float* bq = (const float*)d_in[4];
    const float* Wk = (const float*)d_in[5];
    const float* bk = (const float*)d_in[6];
    const float* Wv = (const float*)d_in[7];
    const float* bv = (const float*)d_in[8];
    const float* Wo = (const float*)d_in[9];
    const float* bo = (const float*)d_in[10];
    float* out = (float*)d_out;

    cudaFuncSetAttribute(gemm_tc,
                         cudaFuncAttributeMaxDynamicSharedMemorySize, GEMM_SMEM);
    cudaFuncSetAttribute(attn_kernel,
                         cudaFuncAttributeMaxDynamicSharedMemorySize, ATTN_SMEM);

    // fused QKV projection (z = 0/1/2 -> Q/K/V)
    gemm_tc<<<dim3(HD / 128, MROWS / 128, 3), 256, GEMM_SMEM>>>(
        h, Wq, Wk, Wv, bq, bk, bv, nullptr, 1);
    // attention
    attn_kernel<<<dim3(BHCOUNT, SQ / 128), 256, ATTN_SMEM>>>(ab, mk);
    // output projection
    gemm_tc<<<dim3(HD / 128, MROWS / 128, 1), 256, GEMM_SMEM>>>(
        nullptr, Wo, Wo, Wo, bo, bo, bo, out, 0);
}